// round 2
// baseline (speedup 1.0000x reference)
#include <cuda_runtime.h>
#include <cuda_bf16.h>
#include <math.h>

// ---------------------------------------------------------------------------
// ConvNet: conv(3->16,5x5) -> hermite -> pool2 -> conv(16->16,5x5) -> hermite
//          -> pool2 -> FC(2704->10).  B=512, input 3x64x64.
// Round 2: packed f32x2 FMA (fma.rn.f32x2) with weights pre-duplicated in
// smem as (w,w) float2 so one LDS.64 gives the packed broadcast weight.
// ---------------------------------------------------------------------------

#define B_IMG 512

__device__ float g_pool1[B_IMG * 16 * 30 * 30];   // after conv1+herm+pool
__device__ float g_pool2[B_IMG * 16 * 13 * 13];   // after conv2+herm+pool

typedef unsigned long long u64;

__device__ __forceinline__ u64 pk2(float lo, float hi) {
    u64 r;
    asm("mov.b64 %0, {%1, %2};" : "=l"(r) : "f"(lo), "f"(hi));
    return r;
}
__device__ __forceinline__ void fma2(u64& acc, u64 a, u64 b) {
    asm("fma.rn.f32x2 %0, %1, %2, %0;" : "+l"(acc) : "l"(a), "l"(b));
}
__device__ __forceinline__ float2 unpk(u64 v) {
    float2 f;
    asm("mov.b64 {%0, %1}, %2;" : "=f"(f.x), "=f"(f.y) : "l"(v));
    return f;
}

__device__ __forceinline__ float herm4(float x, float a0, float a1, float a2,
                                       float a3, float a4) {
    return fmaf(fmaf(fmaf(fmaf(a4, x, a3), x, a2), x, a1), x, a0);
}

// ---------------------------------------------------------------------------
// Kernel 1: conv1 + bias + hermite + maxpool2
// Grid: 512 images * 5 row-bands, 192 threads (180 compute).
// Smem: weights duplicated (1200 float2) first for 8B alignment, then input
// band 3*16*64 floats, then bias.
// ---------------------------------------------------------------------------
__global__ void conv1_fused_kernel(const float* __restrict__ x,
                                   const float* __restrict__ coef,
                                   const float* __restrict__ w,
                                   const float* __restrict__ bias) {
    extern __shared__ float smem[];
    float2* s_w2 = (float2*)smem;                 // 1200 float2 (9600 B)
    float*  s_in = smem + 2 * 1200;               // 3072 floats
    float*  s_b  = s_in + 3 * 16 * 64;            // 16

    const int img  = blockIdx.x / 5;
    const int band = blockIdx.x % 5;
    const int tid  = threadIdx.x;                 // 192

    const float* xim = x + (size_t)img * 3 * 64 * 64;
    const int row0 = band * 12;
    for (int i = tid; i < 3 * 16 * 64; i += 192) {
        int c   = i / (16 * 64);
        int rr  = (i / 64) % 16;
        int col = i % 64;
        s_in[i] = xim[c * 4096 + (row0 + rr) * 64 + col];
    }
    for (int i = tid; i < 1200; i += 192) {
        float wv = w[i];
        s_w2[i] = make_float2(wv, wv);
    }
    if (tid < 16) s_b[tid] = bias[tid];
    __syncthreads();

    const float c0 = __ldg(coef + 0), c1 = __ldg(coef + 1), c2 = __ldg(coef + 2),
                c3 = __ldg(coef + 3), c4 = __ldg(coef + 4);
    const float a0 = c0 - 2.0f * c2 + 12.0f * c4;
    const float a1 = 2.0f * c1 - 12.0f * c3;
    const float a2 = 4.0f * c2 - 48.0f * c4;
    const float a3 = 8.0f * c3;
    const float a4 = 16.0f * c4;

    if (tid < 180) {
        const int pyl = tid / 30;                 // pooled row in band
        const int px  = tid % 30;
        const int oy  = 2 * pyl;
        const int ox  = 2 * px;

        #pragma unroll 1
        for (int chunk = 0; chunk < 2; chunk++) {
            u64 acc01[8], acc23[8];               // (out col0,col1) x (row0,row1)
            #pragma unroll
            for (int co = 0; co < 8; co++) {
                float bv = s_b[chunk * 8 + co];
                u64 bp = pk2(bv, bv);
                acc01[co] = bp;
                acc23[co] = bp;
            }

            #pragma unroll 1
            for (int cin = 0; cin < 3; cin++) {
                const float* rowp = s_in + cin * 16 * 64 + oy * 64 + ox;
                float v[6];
                u64 pa[5], pb[5];
                #pragma unroll
                for (int k = 0; k < 6; k++) v[k] = rowp[k];
                #pragma unroll
                for (int k = 0; k < 5; k++) pa[k] = pk2(v[k], v[k + 1]);
                rowp += 64;
                #pragma unroll
                for (int k = 0; k < 6; k++) v[k] = rowp[k];
                #pragma unroll
                for (int k = 0; k < 5; k++) pb[k] = pk2(v[k], v[k + 1]);

                const u64* wp = (const u64*)(s_w2 + (chunk * 8) * 75 + cin * 25);
                #pragma unroll
                for (int ky = 0; ky < 5; ky++) {
                    if (ky) {
                        #pragma unroll
                        for (int k = 0; k < 5; k++) pa[k] = pb[k];
                        rowp += 64;
                        #pragma unroll
                        for (int k = 0; k < 6; k++) v[k] = rowp[k];
                        #pragma unroll
                        for (int k = 0; k < 5; k++) pb[k] = pk2(v[k], v[k + 1]);
                    }
                    #pragma unroll
                    for (int co = 0; co < 8; co++) {
                        #pragma unroll
                        for (int kx = 0; kx < 5; kx++) {
                            u64 w2 = wp[co * 75 + ky * 5 + kx];
                            fma2(acc01[co], pa[kx], w2);
                            fma2(acc23[co], pb[kx], w2);
                        }
                    }
                }
            }

            const int py = band * 6 + pyl;
            #pragma unroll
            for (int co = 0; co < 8; co++) {
                float2 r01 = unpk(acc01[co]);
                float2 r23 = unpk(acc23[co]);
                float h0 = herm4(r01.x, a0, a1, a2, a3, a4);
                float h1 = herm4(r01.y, a0, a1, a2, a3, a4);
                float h2 = herm4(r23.x, a0, a1, a2, a3, a4);
                float h3 = herm4(r23.y, a0, a1, a2, a3, a4);
                float m = fmaxf(fmaxf(h0, h1), fmaxf(h2, h3));
                g_pool1[((img * 16 + chunk * 8 + co) * 30 + py) * 30 + px] = m;
            }
        }
    }
}

// ---------------------------------------------------------------------------
// Kernel 2: conv2 + bias + hermite + maxpool2
// Grid: 512 blocks (one image each), 256 threads (169 compute).
// Smem: weights duplicated (6400 float2 = 51.2 KB) + input (57.6 KB) + bias
//       = ~109 KB/CTA; two CTAs fit in B200's 228 KB SM carveout.
// ---------------------------------------------------------------------------
__global__ void conv2_fused_kernel(const float* __restrict__ coef,
                                   const float* __restrict__ w,
                                   const float* __restrict__ bias) {
    extern __shared__ float smem[];
    float2* s_w2 = (float2*)smem;                 // 6400 float2 (51200 B)
    float*  s_in = smem + 2 * 6400;               // 14400 floats
    float*  s_b  = s_in + 14400;                  // 16

    const int img = blockIdx.x;
    const int tid = threadIdx.x;                  // 256

    const float* xim = g_pool1 + (size_t)img * 14400;
    for (int i = tid; i < 14400; i += 256) s_in[i] = xim[i];
    for (int i = tid; i < 6400; i += 256) {
        float wv = w[i];
        s_w2[i] = make_float2(wv, wv);
    }
    if (tid < 16) s_b[tid] = bias[tid];
    __syncthreads();

    const float c0 = __ldg(coef + 0), c1 = __ldg(coef + 1), c2 = __ldg(coef + 2),
                c3 = __ldg(coef + 3), c4 = __ldg(coef + 4);
    const float a0 = c0 - 2.0f * c2 + 12.0f * c4;
    const float a1 = 2.0f * c1 - 12.0f * c3;
    const float a2 = 4.0f * c2 - 48.0f * c4;
    const float a3 = 8.0f * c3;
    const float a4 = 16.0f * c4;

    if (tid < 169) {
        const int py = tid / 13;
        const int px = tid % 13;
        const int oy = 2 * py;
        const int ox = 2 * px;

        #pragma unroll 1
        for (int chunk = 0; chunk < 2; chunk++) {
            u64 acc01[8], acc23[8];
            #pragma unroll
            for (int co = 0; co < 8; co++) {
                float bv = s_b[chunk * 8 + co];
                u64 bp = pk2(bv, bv);
                acc01[co] = bp;
                acc23[co] = bp;
            }

            #pragma unroll 1
            for (int cin = 0; cin < 16; cin++) {
                const float* rowp = s_in + cin * 900 + oy * 30 + ox;
                float v[6];
                u64 pa[5], pb[5];
                #pragma unroll
                for (int k = 0; k < 6; k++) v[k] = rowp[k];
                #pragma unroll
                for (int k = 0; k < 5; k++) pa[k] = pk2(v[k], v[k + 1]);
                rowp += 30;
                #pragma unroll
                for (int k = 0; k < 6; k++) v[k] = rowp[k];
                #pragma unroll
                for (int k = 0; k < 5; k++) pb[k] = pk2(v[k], v[k + 1]);

                const u64* wp = (const u64*)(s_w2 + (chunk * 8) * 400 + cin * 25);
                #pragma unroll
                for (int ky = 0; ky < 5; ky++) {
                    if (ky) {
                        #pragma unroll
                        for (int k = 0; k < 5; k++) pa[k] = pb[k];
                        rowp += 30;
                        #pragma unroll
                        for (int k = 0; k < 6; k++) v[k] = rowp[k];
                        #pragma unroll
                        for (int k = 0; k < 5; k++) pb[k] = pk2(v[k], v[k + 1]);
                    }
                    #pragma unroll
                    for (int co = 0; co < 8; co++) {
                        #pragma unroll
                        for (int kx = 0; kx < 5; kx++) {
                            u64 w2 = wp[co * 400 + ky * 5 + kx];
                            fma2(acc01[co], pa[kx], w2);
                            fma2(acc23[co], pb[kx], w2);
                        }
                    }
                }
            }

            #pragma unroll
            for (int co = 0; co < 8; co++) {
                float2 r01 = unpk(acc01[co]);
                float2 r23 = unpk(acc23[co]);
                float h0 = herm4(r01.x, a0, a1, a2, a3, a4);
                float h1 = herm4(r01.y, a0, a1, a2, a3, a4);
                float h2 = herm4(r23.x, a0, a1, a2, a3, a4);
                float h3 = herm4(r23.y, a0, a1, a2, a3, a4);
                float m = fmaxf(fmaxf(h0, h1), fmaxf(h2, h3));
                g_pool2[((img * 16 + chunk * 8 + co) * 13 + py) * 13 + px] = m;
            }
        }
    }
}

// ---------------------------------------------------------------------------
// Kernel 3: FC [512,2704] @ [2704,10]^T + bias
// ---------------------------------------------------------------------------
__global__ void fc_kernel(const float* __restrict__ w,
                          const float* __restrict__ bias,
                          float* __restrict__ out) {
    const int img = blockIdx.x;
    const int tid = threadIdx.x;   // 128

    const float* xv = g_pool2 + (size_t)img * 2704;
    float p[10];
    #pragma unroll
    for (int o = 0; o < 10; o++) p[o] = 0.0f;

    for (int k = tid; k < 2704; k += 128) {
        float v = xv[k];
        #pragma unroll
        for (int o = 0; o < 10; o++) p[o] = fmaf(v, w[o * 2704 + k], p[o]);
    }

    __shared__ float red[4][10];
    const int lane = tid & 31, wrp = tid >> 5;
    #pragma unroll
    for (int o = 0; o < 10; o++) {
        float v = p[o];
        #pragma unroll
        for (int s = 16; s > 0; s >>= 1)
            v += __shfl_down_sync(0xffffffffu, v, s);
        if (lane == 0) red[wrp][o] = v;
    }
    __syncthreads();
    if (tid < 10)
        out[img * 10 + tid] =
            red[0][tid] + red[1][tid] + red[2][tid] + red[3][tid] + bias[tid];
}

// ---------------------------------------------------------------------------
extern "C" void kernel_launch(void* const* d_in, const int* in_sizes, int n_in,
                              void* d_out, int out_size) {
    const float* x       = (const float*)d_in[0];
    const float* coef    = (const float*)d_in[1];
    const float* conv1_w = (const float*)d_in[2];
    const float* conv1_b = (const float*)d_in[3];
    const float* conv2_w = (const float*)d_in[4];
    const float* conv2_b = (const float*)d_in[5];
    const float* fc1_w   = (const float*)d_in[6];
    const float* fc1_b   = (const float*)d_in[7];
    float* out = (float*)d_out;

    const int smem1 = (2 * 1200 + 3 * 16 * 64 + 16) * sizeof(float);   // ~22 KB
    const int smem2 = (2 * 6400 + 14400 + 16) * sizeof(float);         // ~109 KB

    cudaFuncSetAttribute(conv2_fused_kernel,
                         cudaFuncAttributeMaxDynamicSharedMemorySize, smem2);

    conv1_fused_kernel<<<B_IMG * 5, 192, smem1>>>(x, coef, conv1_w, conv1_b);
    conv2_fused_kernel<<<B_IMG, 256, smem2>>>(coef, conv2_w, conv2_b);
    fc_kernel<<<B_IMG, 128>>>(fc1_w, fc1_b, out);
}

// round 4
// speedup vs baseline: 1.0035x; 1.0035x over previous
#include <cuda_runtime.h>
#include <cuda_bf16.h>
#include <math.h>

// ---------------------------------------------------------------------------
// ConvNet: conv(3->16,5x5) -> hermite -> pool2 -> conv(16->16,5x5) -> hermite
//          -> pool2 -> FC(2704->10).  B=512, input 3x64x64.
// Round 3 (re-bench of R2 after infra failure): packed f32x2 FMA
// (fma.rn.f32x2) with weights pre-duplicated in smem as (w,w) float2 so one
// LDS.64 yields the packed broadcast weight.
// ---------------------------------------------------------------------------

#define B_IMG 512

__device__ float g_pool1[B_IMG * 16 * 30 * 30];   // after conv1+herm+pool
__device__ float g_pool2[B_IMG * 16 * 13 * 13];   // after conv2+herm+pool

typedef unsigned long long u64;

__device__ __forceinline__ u64 pk2(float lo, float hi) {
    u64 r;
    asm("mov.b64 %0, {%1, %2};" : "=l"(r) : "f"(lo), "f"(hi));
    return r;
}
__device__ __forceinline__ void fma2(u64& acc, u64 a, u64 b) {
    asm("fma.rn.f32x2 %0, %1, %2, %0;" : "+l"(acc) : "l"(a), "l"(b));
}
__device__ __forceinline__ float2 unpk(u64 v) {
    float2 f;
    asm("mov.b64 {%0, %1}, %2;" : "=f"(f.x), "=f"(f.y) : "l"(v));
    return f;
}

__device__ __forceinline__ float herm4(float x, float a0, float a1, float a2,
                                       float a3, float a4) {
    return fmaf(fmaf(fmaf(fmaf(a4, x, a3), x, a2), x, a1), x, a0);
}

// ---------------------------------------------------------------------------
// Kernel 1: conv1 + bias + hermite + maxpool2
// Grid: 512 images * 5 row-bands, 192 threads (180 compute).
// ---------------------------------------------------------------------------
__global__ void __launch_bounds__(192)
conv1_fused_kernel(const float* __restrict__ x,
                   const float* __restrict__ coef,
                   const float* __restrict__ w,
                   const float* __restrict__ bias) {
    extern __shared__ float smem[];
    float2* s_w2 = (float2*)smem;                 // 1200 float2 (9600 B)
    float*  s_in = smem + 2 * 1200;               // 3072 floats
    float*  s_b  = s_in + 3 * 16 * 64;            // 16

    const int img  = blockIdx.x / 5;
    const int band = blockIdx.x % 5;
    const int tid  = threadIdx.x;                 // 192

    const float* xim = x + (size_t)img * 3 * 64 * 64;
    const int row0 = band * 12;
    // 16 rows x 64 cols per channel; stride between channels in src is 4096.
    for (int i = tid; i < 3 * 16 * 64; i += 192) {
        int c   = i >> 10;              // / 1024
        int rem = i & 1023;
        s_in[i] = xim[c * 4096 + row0 * 64 + rem];
    }
    for (int i = tid; i < 1200; i += 192) {
        float wv = w[i];
        s_w2[i] = make_float2(wv, wv);
    }
    if (tid < 16) s_b[tid] = bias[tid];
    __syncthreads();

    const float c0 = __ldg(coef + 0), c1 = __ldg(coef + 1), c2 = __ldg(coef + 2),
                c3 = __ldg(coef + 3), c4 = __ldg(coef + 4);
    const float a0 = c0 - 2.0f * c2 + 12.0f * c4;
    const float a1 = 2.0f * c1 - 12.0f * c3;
    const float a2 = 4.0f * c2 - 48.0f * c4;
    const float a3 = 8.0f * c3;
    const float a4 = 16.0f * c4;

    if (tid < 180) {
        const int pyl = tid / 30;                 // pooled row in band
        const int px  = tid % 30;
        const int oy  = 2 * pyl;
        const int ox  = 2 * px;

        #pragma unroll 1
        for (int chunk = 0; chunk < 2; chunk++) {
            u64 acc01[8], acc23[8];               // (col0,col1) x (row0,row1)
            #pragma unroll
            for (int co = 0; co < 8; co++) {
                float bv = s_b[chunk * 8 + co];
                u64 bp = pk2(bv, bv);
                acc01[co] = bp;
                acc23[co] = bp;
            }

            #pragma unroll 1
            for (int cin = 0; cin < 3; cin++) {
                const float* rowp = s_in + cin * 16 * 64 + oy * 64 + ox;
                float v[6];
                u64 pa[5], pb[5];
                #pragma unroll
                for (int k = 0; k < 6; k++) v[k] = rowp[k];
                #pragma unroll
                for (int k = 0; k < 5; k++) pa[k] = pk2(v[k], v[k + 1]);
                rowp += 64;
                #pragma unroll
                for (int k = 0; k < 6; k++) v[k] = rowp[k];
                #pragma unroll
                for (int k = 0; k < 5; k++) pb[k] = pk2(v[k], v[k + 1]);

                const u64* wp = (const u64*)(s_w2 + (chunk * 8) * 75 + cin * 25);
                #pragma unroll
                for (int ky = 0; ky < 5; ky++) {
                    if (ky) {
                        #pragma unroll
                        for (int k = 0; k < 5; k++) pa[k] = pb[k];
                        rowp += 64;
                        #pragma unroll
                        for (int k = 0; k < 6; k++) v[k] = rowp[k];
                        #pragma unroll
                        for (int k = 0; k < 5; k++) pb[k] = pk2(v[k], v[k + 1]);
                    }
                    #pragma unroll
                    for (int co = 0; co < 8; co++) {
                        #pragma unroll
                        for (int kx = 0; kx < 5; kx++) {
                            u64 w2 = wp[co * 75 + ky * 5 + kx];
                            fma2(acc01[co], pa[kx], w2);
                            fma2(acc23[co], pb[kx], w2);
                        }
                    }
                }
            }

            const int py = band * 6 + pyl;
            #pragma unroll
            for (int co = 0; co < 8; co++) {
                float2 r01 = unpk(acc01[co]);
                float2 r23 = unpk(acc23[co]);
                float h0 = herm4(r01.x, a0, a1, a2, a3, a4);
                float h1 = herm4(r01.y, a0, a1, a2, a3, a4);
                float h2 = herm4(r23.x, a0, a1, a2, a3, a4);
                float h3 = herm4(r23.y, a0, a1, a2, a3, a4);
                float m = fmaxf(fmaxf(h0, h1), fmaxf(h2, h3));
                g_pool1[((img * 16 + chunk * 8 + co) * 30 + py) * 30 + px] = m;
            }
        }
    }
}

// ---------------------------------------------------------------------------
// Kernel 2: conv2 + bias + hermite + maxpool2
// Grid: 512 blocks (one image each), 256 threads (169 compute).
// Smem: dup weights 51.2 KB + input 57.6 KB + bias = ~109 KB/CTA.
// ---------------------------------------------------------------------------
__global__ void __launch_bounds__(256)
conv2_fused_kernel(const float* __restrict__ coef,
                   const float* __restrict__ w,
                   const float* __restrict__ bias) {
    extern __shared__ float smem[];
    float2* s_w2 = (float2*)smem;                 // 6400 float2 (51200 B)
    float*  s_in = smem + 2 * 6400;               // 14400 floats
    float*  s_b  = s_in + 14400;                  // 16

    const int img = blockIdx.x;
    const int tid = threadIdx.x;                  // 256

    const float* xim = g_pool1 + (size_t)img * 14400;
    for (int i = tid; i < 14400; i += 256) s_in[i] = xim[i];
    for (int i = tid; i < 6400; i += 256) {
        float wv = w[i];
        s_w2[i] = make_float2(wv, wv);
    }
    if (tid < 16) s_b[tid] = bias[tid];
    __syncthreads();

    const float c0 = __ldg(coef + 0), c1 = __ldg(coef + 1), c2 = __ldg(coef + 2),
                c3 = __ldg(coef + 3), c4 = __ldg(coef + 4);
    const float a0 = c0 - 2.0f * c2 + 12.0f * c4;
    const float a1 = 2.0f * c1 - 12.0f * c3;
    const float a2 = 4.0f * c2 - 48.0f * c4;
    const float a3 = 8.0f * c3;
    const float a4 = 16.0f * c4;

    if (tid < 169) {
        const int py = tid / 13;
        const int px = tid % 13;
        const int oy = 2 * py;
        const int ox = 2 * px;

        #pragma unroll 1
        for (int chunk = 0; chunk < 2; chunk++) {
            u64 acc01[8], acc23[8];
            #pragma unroll
            for (int co = 0; co < 8; co++) {
                float bv = s_b[chunk * 8 + co];
                u64 bp = pk2(bv, bv);
                acc01[co] = bp;
                acc23[co] = bp;
            }

            #pragma unroll 1
            for (int cin = 0; cin < 16; cin++) {
                const float* rowp = s_in + cin * 900 + oy * 30 + ox;
                float v[6];
                u64 pa[5], pb[5];
                #pragma unroll
                for (int k = 0; k < 6; k++) v[k] = rowp[k];
                #pragma unroll
                for (int k = 0; k < 5; k++) pa[k] = pk2(v[k], v[k + 1]);
                rowp += 30;
                #pragma unroll
                for (int k = 0; k < 6; k++) v[k] = rowp[k];
                #pragma unroll
                for (int k = 0; k < 5; k++) pb[k] = pk2(v[k], v[k + 1]);

                const u64* wp = (const u64*)(s_w2 + (chunk * 8) * 400 + cin * 25);
                #pragma unroll
                for (int ky = 0; ky < 5; ky++) {
                    if (ky) {
                        #pragma unroll
                        for (int k = 0; k < 5; k++) pa[k] = pb[k];
                        rowp += 30;
                        #pragma unroll
                        for (int k = 0; k < 6; k++) v[k] = rowp[k];
                        #pragma unroll
                        for (int k = 0; k < 5; k++) pb[k] = pk2(v[k], v[k + 1]);
                    }
                    #pragma unroll
                    for (int co = 0; co < 8; co++) {
                        #pragma unroll
                        for (int kx = 0; kx < 5; kx++) {
                            u64 w2 = wp[co * 400 + ky * 5 + kx];
                            fma2(acc01[co], pa[kx], w2);
                            fma2(acc23[co], pb[kx], w2);
                        }
                    }
                }
            }

            #pragma unroll
            for (int co = 0; co < 8; co++) {
                float2 r01 = unpk(acc01[co]);
                float2 r23 = unpk(acc23[co]);
                float h0 = herm4(r01.x, a0, a1, a2, a3, a4);
                float h1 = herm4(r01.y, a0, a1, a2, a3, a4);
                float h2 = herm4(r23.x, a0, a1, a2, a3, a4);
                float h3 = herm4(r23.y, a0, a1, a2, a3, a4);
                float m = fmaxf(fmaxf(h0, h1), fmaxf(h2, h3));
                g_pool2[((img * 16 + chunk * 8 + co) * 13 + py) * 13 + px] = m;
            }
        }
    }
}

// ---------------------------------------------------------------------------
// Kernel 3: FC [512,2704] @ [2704,10]^T + bias
// ---------------------------------------------------------------------------
__global__ void __launch_bounds__(128)
fc_kernel(const float* __restrict__ w,
          const float* __restrict__ bias,
          float* __restrict__ out) {
    const int img = blockIdx.x;
    const int tid = threadIdx.x;   // 128

    const float* xv = g_pool2 + (size_t)img * 2704;
    float p[10];
    #pragma unroll
    for (int o = 0; o < 10; o++) p[o] = 0.0f;

    for (int k = tid; k < 2704; k += 128) {
        float v = xv[k];
        #pragma unroll
        for (int o = 0; o < 10; o++) p[o] = fmaf(v, w[o * 2704 + k], p[o]);
    }

    __shared__ float red[4][10];
    const int lane = tid & 31, wrp = tid >> 5;
    #pragma unroll
    for (int o = 0; o < 10; o++) {
        float v = p[o];
        #pragma unroll
        for (int s = 16; s > 0; s >>= 1)
            v += __shfl_down_sync(0xffffffffu, v, s);
        if (lane == 0) red[wrp][o] = v;
    }
    __syncthreads();
    if (tid < 10)
        out[img * 10 + tid] =
            red[0][tid] + red[1][tid] + red[2][tid] + red[3][tid] + bias[tid];
}

// ---------------------------------------------------------------------------
extern "C" void kernel_launch(void* const* d_in, const int* in_sizes, int n_in,
                              void* d_out, int out_size) {
    const float* x       = (const float*)d_in[0];
    const float* coef    = (const float*)d_in[1];
    const float* conv1_w = (const float*)d_in[2];
    const float* conv1_b = (const float*)d_in[3];
    const float* conv2_w = (const float*)d_in[4];
    const float* conv2_b = (const float*)d_in[5];
    const float* fc1_w   = (const float*)d_in[6];
    const float* fc1_b   = (const float*)d_in[7];
    float* out = (float*)d_out;

    const int smem1 = (2 * 1200 + 3 * 16 * 64 + 16) * sizeof(float);   // ~22 KB
    const int smem2 = (2 * 6400 + 14400 + 16) * sizeof(float);         // ~109 KB

    cudaFuncSetAttribute(conv2_fused_kernel,
                         cudaFuncAttributeMaxDynamicSharedMemorySize, smem2);

    conv1_fused_kernel<<<B_IMG * 5, 192, smem1>>>(x, coef, conv1_w, conv1_b);
    conv2_fused_kernel<<<B_IMG, 256, smem2>>>(coef, conv2_w, conv2_b);
    fc_kernel<<<B_IMG, 128>>>(fc1_w, fc1_b, out);
}

// round 5
// speedup vs baseline: 1.3352x; 1.3306x over previous
#include <cuda_runtime.h>
#include <cuda_bf16.h>
#include <math.h>

// ---------------------------------------------------------------------------
// ConvNet: conv(3->16,5x5) -> hermite -> pool2 -> conv(16->16,5x5) -> hermite
//          -> pool2 -> FC(2704->10).  B=512, input 3x64x64.
// Round 4: revert f32x2 (ALU-pipe regression). Scalar FFMA, issue-slot diet:
//   - weights padded in smem to [co][cin][ky][8] -> LDS.128 + LDS.32 per row
//   - input rows loaded as 3x LDS.64 (always 8B aligned)
// ---------------------------------------------------------------------------

#define B_IMG 512

__device__ float g_pool1[B_IMG * 16 * 30 * 30];   // after conv1+herm+pool
__device__ float g_pool2[B_IMG * 16 * 13 * 13];   // after conv2+herm+pool

__device__ __forceinline__ float herm4(float x, float a0, float a1, float a2,
                                       float a3, float a4) {
    return fmaf(fmaf(fmaf(fmaf(a4, x, a3), x, a2), x, a1), x, a0);
}

// ---------------------------------------------------------------------------
// Kernel 1: conv1 + bias + hermite + maxpool2
// Grid: 512 images * 5 row-bands, 192 threads (180 compute).
// Smem: padded weights 16*3*5*8 = 1920 floats, input 3*16*64 = 3072, bias 16.
// ---------------------------------------------------------------------------
__global__ void __launch_bounds__(192)
conv1_fused_kernel(const float* __restrict__ x,
                   const float* __restrict__ coef,
                   const float* __restrict__ w,
                   const float* __restrict__ bias) {
    extern __shared__ float smem[];
    float* s_w  = smem;                           // 1920 (padded, 16B aligned)
    float* s_in = smem + 1920;                    // 3072
    float* s_b  = s_in + 3 * 16 * 64;             // 16

    const int img  = blockIdx.x / 5;
    const int band = blockIdx.x % 5;
    const int tid  = threadIdx.x;                 // 192

    const float* xim = x + (size_t)img * 3 * 64 * 64;
    const int row0 = band * 12;
    for (int i = tid; i < 3 * 16 * 64; i += 192) {
        int c   = i >> 10;
        int rem = i & 1023;
        s_in[i] = xim[c * 4096 + row0 * 64 + rem];
    }
    // pad weights: dst[((co*3+cin)*5+ky)*8 + kx] = w[co*75+cin*25+ky*5+kx]
    for (int i = tid; i < 1200; i += 192) {
        int co  = i / 75;
        int r   = i % 75;
        int cin = r / 25;
        int r2  = r % 25;
        int ky  = r2 / 5;
        int kx  = r2 % 5;
        s_w[((co * 3 + cin) * 5 + ky) * 8 + kx] = w[i];
    }
    if (tid < 16) s_b[tid] = bias[tid];
    __syncthreads();

    const float c0 = __ldg(coef + 0), c1 = __ldg(coef + 1), c2 = __ldg(coef + 2),
                c3 = __ldg(coef + 3), c4 = __ldg(coef + 4);
    const float a0 = c0 - 2.0f * c2 + 12.0f * c4;
    const float a1 = 2.0f * c1 - 12.0f * c3;
    const float a2 = 4.0f * c2 - 48.0f * c4;
    const float a3 = 8.0f * c3;
    const float a4 = 16.0f * c4;

    if (tid < 180) {
        const int pyl = tid / 30;
        const int px  = tid % 30;
        const int oy  = 2 * pyl;
        const int ox  = 2 * px;

        #pragma unroll 1
        for (int chunk = 0; chunk < 2; chunk++) {
            float acc[8][4];
            #pragma unroll
            for (int co = 0; co < 8; co++) {
                float bv = s_b[chunk * 8 + co];
                acc[co][0] = bv; acc[co][1] = bv; acc[co][2] = bv; acc[co][3] = bv;
            }

            #pragma unroll 1
            for (int cin = 0; cin < 3; cin++) {
                const float* rowp = s_in + cin * 1024 + oy * 64 + ox;
                float va[6], vb[6];
                {
                    const float2* q = (const float2*)rowp;
                    float2 t0 = q[0], t1 = q[1], t2 = q[2];
                    va[0] = t0.x; va[1] = t0.y; va[2] = t1.x;
                    va[3] = t1.y; va[4] = t2.x; va[5] = t2.y;
                }
                rowp += 64;
                {
                    const float2* q = (const float2*)rowp;
                    float2 t0 = q[0], t1 = q[1], t2 = q[2];
                    vb[0] = t0.x; vb[1] = t0.y; vb[2] = t1.x;
                    vb[3] = t1.y; vb[4] = t2.x; vb[5] = t2.y;
                }

                // weight base for this (chunk, cin): co stride = 3*5*8 = 120
                const float* wbase = s_w + ((chunk * 8) * 3 + cin) * 40;
                #pragma unroll
                for (int ky = 0; ky < 5; ky++) {
                    if (ky) {
                        #pragma unroll
                        for (int k = 0; k < 6; k++) va[k] = vb[k];
                        rowp += 64;
                        const float2* q = (const float2*)rowp;
                        float2 t0 = q[0], t1 = q[1], t2 = q[2];
                        vb[0] = t0.x; vb[1] = t0.y; vb[2] = t1.x;
                        vb[3] = t1.y; vb[4] = t2.x; vb[5] = t2.y;
                    }
                    #pragma unroll
                    for (int co = 0; co < 8; co++) {
                        const float* wrow = wbase + co * 120 + ky * 8;
                        float4 w03 = *(const float4*)wrow;
                        float  w4  = wrow[4];
                        acc[co][0] = fmaf(va[0], w03.x, acc[co][0]);
                        acc[co][1] = fmaf(va[1], w03.x, acc[co][1]);
                        acc[co][2] = fmaf(vb[0], w03.x, acc[co][2]);
                        acc[co][3] = fmaf(vb[1], w03.x, acc[co][3]);
                        acc[co][0] = fmaf(va[1], w03.y, acc[co][0]);
                        acc[co][1] = fmaf(va[2], w03.y, acc[co][1]);
                        acc[co][2] = fmaf(vb[1], w03.y, acc[co][2]);
                        acc[co][3] = fmaf(vb[2], w03.y, acc[co][3]);
                        acc[co][0] = fmaf(va[2], w03.z, acc[co][0]);
                        acc[co][1] = fmaf(va[3], w03.z, acc[co][1]);
                        acc[co][2] = fmaf(vb[2], w03.z, acc[co][2]);
                        acc[co][3] = fmaf(vb[3], w03.z, acc[co][3]);
                        acc[co][0] = fmaf(va[3], w03.w, acc[co][0]);
                        acc[co][1] = fmaf(va[4], w03.w, acc[co][1]);
                        acc[co][2] = fmaf(vb[3], w03.w, acc[co][2]);
                        acc[co][3] = fmaf(vb[4], w03.w, acc[co][3]);
                        acc[co][0] = fmaf(va[4], w4, acc[co][0]);
                        acc[co][1] = fmaf(va[5], w4, acc[co][1]);
                        acc[co][2] = fmaf(vb[4], w4, acc[co][2]);
                        acc[co][3] = fmaf(vb[5], w4, acc[co][3]);
                    }
                }
            }

            const int py = band * 6 + pyl;
            #pragma unroll
            for (int co = 0; co < 8; co++) {
                float h0 = herm4(acc[co][0], a0, a1, a2, a3, a4);
                float h1 = herm4(acc[co][1], a0, a1, a2, a3, a4);
                float h2 = herm4(acc[co][2], a0, a1, a2, a3, a4);
                float h3 = herm4(acc[co][3], a0, a1, a2, a3, a4);
                float m = fmaxf(fmaxf(h0, h1), fmaxf(h2, h3));
                g_pool1[((img * 16 + chunk * 8 + co) * 30 + py) * 30 + px] = m;
            }
        }
    }
}

// ---------------------------------------------------------------------------
// Kernel 2: conv2 + bias + hermite + maxpool2
// Grid: 512 blocks (one image), 192 threads (169 compute).
// Smem: padded weights 16*16*5*8 = 10240 floats (40KB) + input 14400 (57.6KB)
//       + bias = ~98.6 KB -> 2 CTAs/SM.
// ---------------------------------------------------------------------------
__global__ void __launch_bounds__(192)
conv2_fused_kernel(const float* __restrict__ coef,
                   const float* __restrict__ w,
                   const float* __restrict__ bias) {
    extern __shared__ float smem[];
    float* s_w  = smem;                           // 10240
    float* s_in = smem + 10240;                   // 14400
    float* s_b  = s_in + 14400;                   // 16

    const int img = blockIdx.x;
    const int tid = threadIdx.x;                  // 192

    const float* xim = g_pool1 + (size_t)img * 14400;
    for (int i = tid; i < 14400; i += 192) s_in[i] = xim[i];
    // pad: dst[((co*16+cin)*5+ky)*8 + kx] = w[co*400+cin*25+ky*5+kx]
    for (int i = tid; i < 6400; i += 192) {
        int co  = i / 400;
        int r   = i % 400;
        int cin = r / 25;
        int r2  = r % 25;
        int ky  = r2 / 5;
        int kx  = r2 % 5;
        s_w[((co * 16 + cin) * 5 + ky) * 8 + kx] = w[i];
    }
    if (tid < 16) s_b[tid] = bias[tid];
    __syncthreads();

    const float c0 = __ldg(coef + 0), c1 = __ldg(coef + 1), c2 = __ldg(coef + 2),
                c3 = __ldg(coef + 3), c4 = __ldg(coef + 4);
    const float a0 = c0 - 2.0f * c2 + 12.0f * c4;
    const float a1 = 2.0f * c1 - 12.0f * c3;
    const float a2 = 4.0f * c2 - 48.0f * c4;
    const float a3 = 8.0f * c3;
    const float a4 = 16.0f * c4;

    if (tid < 169) {
        const int py = tid / 13;
        const int px = tid % 13;
        const int oy = 2 * py;
        const int ox = 2 * px;

        #pragma unroll 1
        for (int chunk = 0; chunk < 2; chunk++) {
            float acc[8][4];
            #pragma unroll
            for (int co = 0; co < 8; co++) {
                float bv = s_b[chunk * 8 + co];
                acc[co][0] = bv; acc[co][1] = bv; acc[co][2] = bv; acc[co][3] = bv;
            }

            #pragma unroll 1
            for (int cin = 0; cin < 16; cin++) {
                const float* rowp = s_in + cin * 900 + oy * 30 + ox;
                float va[6], vb[6];
                {
                    const float2* q = (const float2*)rowp;
                    float2 t0 = q[0], t1 = q[1], t2 = q[2];
                    va[0] = t0.x; va[1] = t0.y; va[2] = t1.x;
                    va[3] = t1.y; va[4] = t2.x; va[5] = t2.y;
                }
                rowp += 30;
                {
                    const float2* q = (const float2*)rowp;
                    float2 t0 = q[0], t1 = q[1], t2 = q[2];
                    vb[0] = t0.x; vb[1] = t0.y; vb[2] = t1.x;
                    vb[3] = t1.y; vb[4] = t2.x; vb[5] = t2.y;
                }

                // co stride = 16*5*8 = 640
                const float* wbase = s_w + ((chunk * 8) * 16 + cin) * 40;
                #pragma unroll
                for (int ky = 0; ky < 5; ky++) {
                    if (ky) {
                        #pragma unroll
                        for (int k = 0; k < 6; k++) va[k] = vb[k];
                        rowp += 30;
                        const float2* q = (const float2*)rowp;
                        float2 t0 = q[0], t1 = q[1], t2 = q[2];
                        vb[0] = t0.x; vb[1] = t0.y; vb[2] = t1.x;
                        vb[3] = t1.y; vb[4] = t2.x; vb[5] = t2.y;
                    }
                    #pragma unroll
                    for (int co = 0; co < 8; co++) {
                        const float* wrow = wbase + co * 640 + ky * 8;
                        float4 w03 = *(const float4*)wrow;
                        float  w4  = wrow[4];
                        acc[co][0] = fmaf(va[0], w03.x, acc[co][0]);
                        acc[co][1] = fmaf(va[1], w03.x, acc[co][1]);
                        acc[co][2] = fmaf(vb[0], w03.x, acc[co][2]);
                        acc[co][3] = fmaf(vb[1], w03.x, acc[co][3]);
                        acc[co][0] = fmaf(va[1], w03.y, acc[co][0]);
                        acc[co][1] = fmaf(va[2], w03.y, acc[co][1]);
                        acc[co][2] = fmaf(vb[1], w03.y, acc[co][2]);
                        acc[co][3] = fmaf(vb[2], w03.y, acc[co][3]);
                        acc[co][0] = fmaf(va[2], w03.z, acc[co][0]);
                        acc[co][1] = fmaf(va[3], w03.z, acc[co][1]);
                        acc[co][2] = fmaf(vb[2], w03.z, acc[co][2]);
                        acc[co][3] = fmaf(vb[3], w03.z, acc[co][3]);
                        acc[co][0] = fmaf(va[3], w03.w, acc[co][0]);
                        acc[co][1] = fmaf(va[4], w03.w, acc[co][1]);
                        acc[co][2] = fmaf(vb[3], w03.w, acc[co][2]);
                        acc[co][3] = fmaf(vb[4], w03.w, acc[co][3]);
                        acc[co][0] = fmaf(va[4], w4, acc[co][0]);
                        acc[co][1] = fmaf(va[5], w4, acc[co][1]);
                        acc[co][2] = fmaf(vb[4], w4, acc[co][2]);
                        acc[co][3] = fmaf(vb[5], w4, acc[co][3]);
                    }
                }
            }

            #pragma unroll
            for (int co = 0; co < 8; co++) {
                float h0 = herm4(acc[co][0], a0, a1, a2, a3, a4);
                float h1 = herm4(acc[co][1], a0, a1, a2, a3, a4);
                float h2 = herm4(acc[co][2], a0, a1, a2, a3, a4);
                float h3 = herm4(acc[co][3], a0, a1, a2, a3, a4);
                float m = fmaxf(fmaxf(h0, h1), fmaxf(h2, h3));
                g_pool2[((img * 16 + chunk * 8 + co) * 13 + py) * 13 + px] = m;
            }
        }
    }
}

// ---------------------------------------------------------------------------
// Kernel 3: FC [512,2704] @ [2704,10]^T + bias
// ---------------------------------------------------------------------------
__global__ void __launch_bounds__(128)
fc_kernel(const float* __restrict__ w,
          const float* __restrict__ bias,
          float* __restrict__ out) {
    const int img = blockIdx.x;
    const int tid = threadIdx.x;   // 128

    const float* xv = g_pool2 + (size_t)img * 2704;
    float p[10];
    #pragma unroll
    for (int o = 0; o < 10; o++) p[o] = 0.0f;

    for (int k = tid; k < 2704; k += 128) {
        float v = xv[k];
        #pragma unroll
        for (int o = 0; o < 10; o++) p[o] = fmaf(v, w[o * 2704 + k], p[o]);
    }

    __shared__ float red[4][10];
    const int lane = tid & 31, wrp = tid >> 5;
    #pragma unroll
    for (int o = 0; o < 10; o++) {
        float v = p[o];
        #pragma unroll
        for (int s = 16; s > 0; s >>= 1)
            v += __shfl_down_sync(0xffffffffu, v, s);
        if (lane == 0) red[wrp][o] = v;
    }
    __syncthreads();
    if (tid < 10)
        out[img * 10 + tid] =
            red[0][tid] + red[1][tid] + red[2][tid] + red[3][tid] + bias[tid];
}

// ---------------------------------------------------------------------------
extern "C" void kernel_launch(void* const* d_in, const int* in_sizes, int n_in,
                              void* d_out, int out_size) {
    const float* x       = (const float*)d_in[0];
    const float* coef    = (const float*)d_in[1];
    const float* conv1_w = (const float*)d_in[2];
    const float* conv1_b = (const float*)d_in[3];
    const float* conv2_w = (const float*)d_in[4];
    const float* conv2_b = (const float*)d_in[5];
    const float* fc1_w   = (const float*)d_in[6];
    const float* fc1_b   = (const float*)d_in[7];
    float* out = (float*)d_out;

    const int smem1 = (1920 + 3 * 16 * 64 + 16) * sizeof(float);   // ~20 KB
    const int smem2 = (10240 + 14400 + 16) * sizeof(float);        // ~98.6 KB

    cudaFuncSetAttribute(conv2_fused_kernel,
                         cudaFuncAttributeMaxDynamicSharedMemorySize, smem2);

    conv1_fused_kernel<<<B_IMG * 5, 192, smem1>>>(x, coef, conv1_w, conv1_b);
    conv2_fused_kernel<<<B_IMG, 192, smem2>>>(coef, conv2_w, conv2_b);
    fc_kernel<<<B_IMG, 128>>>(fc1_w, fc1_b, out);
}